// round 3
// baseline (speedup 1.0000x reference)
#include <cuda_runtime.h>
#include <math.h>

#define N_NODES 100000
#define N_EDGES 1600000
#define IN_DIM  64
#define EMB     128
#define ED      32

// Scratch (static device allocations are allowed)
__device__ float g_agg[2][(size_t)N_NODES * IN_DIM];   // [0]=in (agg@dst), [1]=out (agg@src)
__device__ float g_t[2][(size_t)N_NODES * EMB];        // gelu(h@W1+b1) per direction

// ---------------------------------------------------------------------------
// zero the aggregation buffers
// ---------------------------------------------------------------------------
__global__ void zero_kernel() {
    size_t total = (size_t)2 * N_NODES * IN_DIM / 4;
    float4* p = (float4*)g_agg;
    float4 z = make_float4(0.f, 0.f, 0.f, 0.f);
    for (size_t i = (size_t)blockIdx.x * blockDim.x + threadIdx.x; i < total;
         i += (size_t)gridDim.x * blockDim.x)
        p[i] = z;
}

// ---------------------------------------------------------------------------
// Edge kernel: warp-per-edge, direction-specialized by blockIdx.y.
// msg = relu(x[gather] + ea@We + be); lanes pair up so only even lanes issue
// red.global.add.v4.f32 (halves atomic lane-ops vs v2-per-lane).
// ---------------------------------------------------------------------------
__global__ __launch_bounds__(256, 2) void edge_kernel(
    const float2* __restrict__ x2,        // x viewed as [N_NODES][32] float2
    const int* __restrict__ ei,           // [2][N_EDGES] int32
    const float* __restrict__ ea,         // [N_EDGES][32]
    const float2* __restrict__ We_in2,    // [32][32] float2 view of [32][64]
    const float2* __restrict__ be_in2,    // [32]
    const float2* __restrict__ We_out2,
    const float2* __restrict__ be_out2)
{
    const int dir  = blockIdx.y;          // 0 = conv_in, 1 = conv_out
    const int lane = threadIdx.x & 31;
    const int w    = threadIdx.x >> 5;

    const float2* We2 = dir ? We_out2 : We_in2;
    const float2  bias = dir ? be_out2[lane] : be_in2[lane];
    // conv_in:  gather src (ei[0]), scatter dst (ei[1])
    // conv_out: gather dst, scatter src
    const int* gidx = dir ? (ei + N_EDGES) : ei;
    const int* sidx = dir ? ei : (ei + N_EDGES);
    float* __restrict__ agg = g_agg[dir];

    float2 wreg[32];
#pragma unroll
    for (int k = 0; k < 32; k++) wreg[k] = We2[k * 32 + lane];

    __shared__ float sEa[8][32];

    const int warpGlobal = blockIdx.x * 8 + w;
    const int nwarps = gridDim.x * 8;

    for (int e = warpGlobal; e < N_EDGES; e += nwarps) {
        int s = gidx[e];
        int d = sidx[e];
        sEa[w][lane] = ea[(size_t)e * 32 + lane];
        __syncwarp();

        float2 acc = x2[(size_t)s * 32 + lane];
        acc.x += bias.x;
        acc.y += bias.y;
#pragma unroll
        for (int k = 0; k < 32; k++) {
            float a = sEa[w][k];
            acc.x = fmaf(a, wreg[k].x, acc.x);
            acc.y = fmaf(a, wreg[k].y, acc.y);
        }
        acc.x = fmaxf(acc.x, 0.f);
        acc.y = fmaxf(acc.y, 0.f);

        // pair lanes: even lane takes odd neighbor's pair -> one red.v4 per 2 lanes
        float ox = __shfl_down_sync(0xffffffffu, acc.x, 1);
        float oy = __shfl_down_sync(0xffffffffu, acc.y, 1);
        if (!(lane & 1)) {
            float* p = agg + (size_t)d * 64 + 2 * lane;   // dims [2*lane .. 2*lane+3]
            asm volatile("red.global.add.v4.f32 [%0], {%1, %2, %3, %4};"
                         :: "l"(p), "f"(acc.x), "f"(acc.y), "f"(ox), "f"(oy)
                         : "memory");
        }
        __syncwarp();
    }
}

// ---------------------------------------------------------------------------
// GEMM micro-framework: 64(M) x 128(N) block tile, 256 threads, 4x8 microtile,
// K processed in 32-wide chunks. A optionally has an addend and a scale.
// sAT rows padded to 68 floats (272B) so av loads are a single LDS.128.
// ---------------------------------------------------------------------------
__device__ __forceinline__ void gemm_chunk(
    const float* __restrict__ A, const float* __restrict__ Aadd, int lda4,
    const float* __restrict__ W, int k0, int m0, float scale,
    float (*sAT)[68], float (*sW)[128], float acc[4][8], int tid)
{
    // Stage A chunk: 64 rows x 32 cols, transposed into sAT[k][row]
    const float4* A4  = (const float4*)A;
    const float4* Aa4 = (const float4*)Aadd;
#pragma unroll
    for (int it = 0; it < 2; ++it) {
        int idx = it * 256 + tid;       // 0..511
        int r   = idx >> 3;             // row within tile
        int cq  = idx & 7;              // float4 index within 32-col chunk
        float4 v = make_float4(0.f, 0.f, 0.f, 0.f);
        int gr = m0 + r;
        if (gr < N_NODES) {
            v = A4[(size_t)gr * lda4 + (k0 >> 2) + cq];
            if (Aadd) {
                float4 u = Aa4[(size_t)gr * lda4 + (k0 >> 2) + cq];
                v.x += u.x; v.y += u.y; v.z += u.z; v.w += u.w;
            }
            v.x *= scale; v.y *= scale; v.z *= scale; v.w *= scale;
        }
        sAT[cq * 4 + 0][r] = v.x;
        sAT[cq * 4 + 1][r] = v.y;
        sAT[cq * 4 + 2][r] = v.z;
        sAT[cq * 4 + 3][r] = v.w;
    }
    // Stage W chunk: rows k0..k0+31 of [K][128]
    const float4* W4 = (const float4*)W;
#pragma unroll
    for (int it = 0; it < 4; ++it) {
        int idx = it * 256 + tid;       // 0..1023
        int kr  = idx >> 5;
        int cq  = idx & 31;
        *(float4*)&sW[kr][cq * 4] = W4[(size_t)(k0 + kr) * 32 + cq];
    }
    __syncthreads();

    const int rg = (tid >> 4) * 4;
    const int cg = (tid & 15) * 8;
#pragma unroll
    for (int k = 0; k < 32; k++) {
        float av[4];
        *(float4*)&av[0] = *(const float4*)&sAT[k][rg];   // aligned: 272B row pitch
        float bv[8];
        *(float4*)&bv[0] = *(const float4*)&sW[k][cg];
        *(float4*)&bv[4] = *(const float4*)&sW[k][cg + 4];
#pragma unroll
        for (int i = 0; i < 4; i++)
#pragma unroll
            for (int j = 0; j < 8; j++)
                acc[i][j] = fmaf(av[i], bv[j], acc[i][j]);
    }
    __syncthreads();
}

__device__ __forceinline__ float gelu_exact(float v) {
    return 0.5f * v * (1.f + erff(v * 0.70710678118654752f));
}

// ---------------------------------------------------------------------------
// N1: t[dir] = gelu((x + agg[dir]) @ W1 + b1)
// ---------------------------------------------------------------------------
__global__ __launch_bounds__(256) void n1_kernel(
    const float* __restrict__ x,
    const float* __restrict__ W1_in,  const float* __restrict__ b1_in,
    const float* __restrict__ W1_out, const float* __restrict__ b1_out)
{
    const int dir = blockIdx.y;
    const float* W1 = dir ? W1_out : W1_in;
    const float* b1 = dir ? b1_out : b1_in;
    const float* agg = g_agg[dir];
    float* tptr = g_t[dir];

    __shared__ float sAT[32][68];
    __shared__ float sW[32][128];
    float acc[4][8];
#pragma unroll
    for (int i = 0; i < 4; i++)
#pragma unroll
        for (int j = 0; j < 8; j++) acc[i][j] = 0.f;

    const int tid = threadIdx.x;
    const int m0  = blockIdx.x * 64;

    gemm_chunk(x, agg, 16, W1,  0, m0, 1.f, sAT, sW, acc, tid);
    gemm_chunk(x, agg, 16, W1, 32, m0, 1.f, sAT, sW, acc, tid);

    const int rg = (tid >> 4) * 4;
    const int cg = (tid & 15) * 8;
#pragma unroll
    for (int i = 0; i < 4; i++) {
        int gr = m0 + rg + i;
        if (gr < N_NODES) {
            float o[8];
#pragma unroll
            for (int j = 0; j < 8; j++)
                o[j] = gelu_exact(acc[i][j] + b1[cg + j]);
            *(float4*)&tptr[(size_t)gr * EMB + cg]     = *(float4*)&o[0];
            *(float4*)&tptr[(size_t)gr * EMB + cg + 4] = *(float4*)&o[4];
        }
    }
}

// ---------------------------------------------------------------------------
// N2: out = 0.5*(t_out@W2_out + b2_out) + 0.5*(t_in@W2_in + b2_in) + x@Wr + br
// ---------------------------------------------------------------------------
__global__ __launch_bounds__(256) void n2_kernel(
    const float* __restrict__ x,
    const float* __restrict__ W2_in,  const float* __restrict__ b2_in,
    const float* __restrict__ W2_out, const float* __restrict__ b2_out,
    const float* __restrict__ Wr,     const float* __restrict__ br,
    float* __restrict__ out)
{
    __shared__ float sAT[32][68];
    __shared__ float sW[32][128];
    float acc[4][8];
#pragma unroll
    for (int i = 0; i < 4; i++)
#pragma unroll
        for (int j = 0; j < 8; j++) acc[i][j] = 0.f;

    const int tid = threadIdx.x;
    const int m0  = blockIdx.x * 64;

#pragma unroll 1
    for (int k0 = 0; k0 < 128; k0 += 32)
        gemm_chunk(g_t[1], nullptr, 32, W2_out, k0, m0, 0.5f, sAT, sW, acc, tid);
#pragma unroll 1
    for (int k0 = 0; k0 < 128; k0 += 32)
        gemm_chunk(g_t[0], nullptr, 32, W2_in, k0, m0, 0.5f, sAT, sW, acc, tid);
#pragma unroll 1
    for (int k0 = 0; k0 < 64; k0 += 32)
        gemm_chunk(x, nullptr, 16, Wr, k0, m0, 1.f, sAT, sW, acc, tid);

    const int rg = (tid >> 4) * 4;
    const int cg = (tid & 15) * 8;
#pragma unroll
    for (int i = 0; i < 4; i++) {
        int gr = m0 + rg + i;
        if (gr < N_NODES) {
            float o[8];
#pragma unroll
            for (int j = 0; j < 8; j++) {
                float bias = 0.5f * (b2_out[cg + j] + b2_in[cg + j]) + br[cg + j];
                o[j] = acc[i][j] + bias;
            }
            *(float4*)&out[(size_t)gr * EMB + cg]     = *(float4*)&o[0];
            *(float4*)&out[(size_t)gr * EMB + cg + 4] = *(float4*)&o[4];
        }
    }
}

// ---------------------------------------------------------------------------
// launch
// ---------------------------------------------------------------------------
extern "C" void kernel_launch(void* const* d_in, const int* in_sizes, int n_in,
                              void* d_out, int out_size)
{
    const float* x      = (const float*)d_in[0];
    const int*   ei     = (const int*)d_in[1];
    const float* ea     = (const float*)d_in[2];
    const float* We_in  = (const float*)d_in[3];
    const float* be_in  = (const float*)d_in[4];
    const float* W1_in  = (const float*)d_in[5];
    const float* b1_in  = (const float*)d_in[6];
    const float* W2_in  = (const float*)d_in[7];
    const float* b2_in  = (const float*)d_in[8];
    const float* We_out = (const float*)d_in[9];
    const float* be_out = (const float*)d_in[10];
    const float* W1_out = (const float*)d_in[11];
    const float* b1_out = (const float*)d_in[12];
    const float* W2_out = (const float*)d_in[13];
    const float* b2_out = (const float*)d_in[14];
    const float* Wr     = (const float*)d_in[15];
    const float* br     = (const float*)d_in[16];
    float* out = (float*)d_out;

    zero_kernel<<<1024, 256>>>();

    dim3 egrid(2368, 2);
    edge_kernel<<<egrid, 256>>>(
        (const float2*)x, ei, ea,
        (const float2*)We_in,  (const float2*)be_in,
        (const float2*)We_out, (const float2*)be_out);

    dim3 ngrid((N_NODES + 63) / 64, 2);
    n1_kernel<<<ngrid, 256>>>(x, W1_in, b1_in, W1_out, b1_out);

    n2_kernel<<<(N_NODES + 63) / 64, 256>>>(
        x, W2_in, b2_in, W2_out, b2_out, Wr, br, out);
}

// round 4
// speedup vs baseline: 1.5481x; 1.5481x over previous
#include <cuda_runtime.h>
#include <math.h>

#define N_NODES 100000
#define N_EDGES 1600000
#define IN_DIM  64
#define EMB     128
#define ED      32

// Scratch (static device allocations are allowed)
__device__ float g_agg[2][(size_t)N_NODES * IN_DIM];   // [0]=in (agg@dst), [1]=out (agg@src)
__device__ float g_t[2][(size_t)N_NODES * EMB];        // gelu(h@W1+b1) per direction

// ---------------------------------------------------------------------------
// zero the aggregation buffers
// ---------------------------------------------------------------------------
__global__ void zero_kernel() {
    size_t total = (size_t)2 * N_NODES * IN_DIM / 4;
    float4* p = (float4*)g_agg;
    float4 z = make_float4(0.f, 0.f, 0.f, 0.f);
    for (size_t i = (size_t)blockIdx.x * blockDim.x + threadIdx.x; i < total;
         i += (size_t)gridDim.x * blockDim.x)
        p[i] = z;
}

// ---------------------------------------------------------------------------
// Edge kernel: warp-per-edge, 2 edges in flight per warp per iteration.
// msg = relu(x[gather] + ea@We + be), red.v2 per lane into agg[scatter].
// Weights register-resident (thread lane owns output dims {2l, 2l+1}).
// ---------------------------------------------------------------------------
__global__ __launch_bounds__(256, 2) void edge_kernel(
    const float2* __restrict__ x2,        // x viewed as [N_NODES][32] float2
    const int* __restrict__ ei,           // [2][N_EDGES] int32
    const float* __restrict__ ea,         // [N_EDGES][32]
    const float2* __restrict__ We_in2,    // [32][32] float2 view of [32][64]
    const float2* __restrict__ be_in2,    // [32]
    const float2* __restrict__ We_out2,
    const float2* __restrict__ be_out2)
{
    const int dir  = blockIdx.y;          // 0 = conv_in, 1 = conv_out
    const int lane = threadIdx.x & 31;
    const int w    = threadIdx.x >> 5;

    const float2* We2 = dir ? We_out2 : We_in2;
    const float2  bias = dir ? be_out2[lane] : be_in2[lane];
    // conv_in:  gather src (ei[0]), scatter dst (ei[1])
    // conv_out: gather dst, scatter src
    const int* gidx = dir ? (ei + N_EDGES) : ei;
    const int* sidx = dir ? ei : (ei + N_EDGES);
    float* __restrict__ agg = g_agg[dir];

    float2 wreg[32];
#pragma unroll
    for (int k = 0; k < 32; k++) wreg[k] = We2[k * 32 + lane];

    __shared__ float sEa[8][2][32];

    const int warpGlobal = blockIdx.x * 8 + w;
    const int nwarps = gridDim.x * 8;

    for (int e1 = warpGlobal; e1 < N_EDGES; e1 += 2 * nwarps) {
        const int e2 = e1 + nwarps;
        const bool has2 = (e2 < N_EDGES);

        // issue all loads up front (max MLP)
        int s1 = gidx[e1];
        int d1 = sidx[e1];
        int s2 = has2 ? gidx[e2] : s1;
        int d2 = has2 ? sidx[e2] : d1;
        float ea1 = ea[(size_t)e1 * 32 + lane];
        float ea2 = has2 ? ea[(size_t)e2 * 32 + lane] : 0.f;
        float2 xa = x2[(size_t)s1 * 32 + lane];
        float2 xb = x2[(size_t)s2 * 32 + lane];

        sEa[w][0][lane] = ea1;
        sEa[w][1][lane] = ea2;
        __syncwarp();

        float2 acc1, acc2;
        acc1.x = xa.x + bias.x;  acc1.y = xa.y + bias.y;
        acc2.x = xb.x + bias.x;  acc2.y = xb.y + bias.y;
#pragma unroll
        for (int k = 0; k < 32; k++) {
            float a1 = sEa[w][0][k];
            float a2 = sEa[w][1][k];
            acc1.x = fmaf(a1, wreg[k].x, acc1.x);
            acc1.y = fmaf(a1, wreg[k].y, acc1.y);
            acc2.x = fmaf(a2, wreg[k].x, acc2.x);
            acc2.y = fmaf(a2, wreg[k].y, acc2.y);
        }
        acc1.x = fmaxf(acc1.x, 0.f);  acc1.y = fmaxf(acc1.y, 0.f);
        acc2.x = fmaxf(acc2.x, 0.f);  acc2.y = fmaxf(acc2.y, 0.f);

        float* p1 = agg + (size_t)d1 * 64 + 2 * lane;
        asm volatile("red.global.add.v2.f32 [%0], {%1, %2};"
                     :: "l"(p1), "f"(acc1.x), "f"(acc1.y) : "memory");
        if (has2) {
            float* p2 = agg + (size_t)d2 * 64 + 2 * lane;
            asm volatile("red.global.add.v2.f32 [%0], {%1, %2};"
                         :: "l"(p2), "f"(acc2.x), "f"(acc2.y) : "memory");
        }
        __syncwarp();
    }
}

// ---------------------------------------------------------------------------
// GEMM micro-framework: 64(M) x 128(N) block tile, 256 threads, 4x8 microtile,
// K processed in 32-wide chunks. A optionally has an addend and a scale.
// ---------------------------------------------------------------------------
__device__ __forceinline__ void gemm_chunk(
    const float* __restrict__ A, const float* __restrict__ Aadd, int lda4,
    const float* __restrict__ W, int k0, int m0, float scale,
    float (*sAT)[65], float (*sW)[128], float acc[4][8], int tid)
{
    // Stage A chunk: 64 rows x 32 cols, transposed into sAT[k][row]
    const float4* A4  = (const float4*)A;
    const float4* Aa4 = (const float4*)Aadd;
#pragma unroll
    for (int it = 0; it < 2; ++it) {
        int idx = it * 256 + tid;       // 0..511
        int r   = idx >> 3;             // row within tile
        int cq  = idx & 7;              // float4 index within 32-col chunk
        float4 v = make_float4(0.f, 0.f, 0.f, 0.f);
        int gr = m0 + r;
        if (gr < N_NODES) {
            v = A4[(size_t)gr * lda4 + (k0 >> 2) + cq];
            if (Aadd) {
                float4 u = Aa4[(size_t)gr * lda4 + (k0 >> 2) + cq];
                v.x += u.x; v.y += u.y; v.z += u.z; v.w += u.w;
            }
            v.x *= scale; v.y *= scale; v.z *= scale; v.w *= scale;
        }
        sAT[cq * 4 + 0][r] = v.x;
        sAT[cq * 4 + 1][r] = v.y;
        sAT[cq * 4 + 2][r] = v.z;
        sAT[cq * 4 + 3][r] = v.w;
    }
    // Stage W chunk: rows k0..k0+31 of [K][128]
    const float4* W4 = (const float4*)W;
#pragma unroll
    for (int it = 0; it < 4; ++it) {
        int idx = it * 256 + tid;       // 0..1023
        int kr  = idx >> 5;
        int cq  = idx & 31;
        *(float4*)&sW[kr][cq * 4] = W4[(size_t)(k0 + kr) * 32 + cq];
    }
    __syncthreads();

    const int rg = (tid >> 4) * 4;
    const int cg = (tid & 15) * 8;
#pragma unroll
    for (int k = 0; k < 32; k++) {
        float av[4];
        av[0] = sAT[k][rg + 0];
        av[1] = sAT[k][rg + 1];
        av[2] = sAT[k][rg + 2];
        av[3] = sAT[k][rg + 3];
        float bv[8];
        *(float4*)&bv[0] = *(const float4*)&sW[k][cg];
        *(float4*)&bv[4] = *(const float4*)&sW[k][cg + 4];
#pragma unroll
        for (int i = 0; i < 4; i++)
#pragma unroll
            for (int j = 0; j < 8; j++)
                acc[i][j] = fmaf(av[i], bv[j], acc[i][j]);
    }
    __syncthreads();
}

__device__ __forceinline__ float gelu_exact(float v) {
    return 0.5f * v * (1.f + erff(v * 0.70710678118654752f));
}

// ---------------------------------------------------------------------------
// N1: t[dir] = gelu((x + agg[dir]) @ W1 + b1)
// ---------------------------------------------------------------------------
__global__ __launch_bounds__(256) void n1_kernel(
    const float* __restrict__ x,
    const float* __restrict__ W1_in,  const float* __restrict__ b1_in,
    const float* __restrict__ W1_out, const float* __restrict__ b1_out)
{
    const int dir = blockIdx.y;
    const float* W1 = dir ? W1_out : W1_in;
    const float* b1 = dir ? b1_out : b1_in;
    const float* agg = g_agg[dir];
    float* tptr = g_t[dir];

    __shared__ float sAT[32][65];
    __shared__ float sW[32][128];
    float acc[4][8];
#pragma unroll
    for (int i = 0; i < 4; i++)
#pragma unroll
        for (int j = 0; j < 8; j++) acc[i][j] = 0.f;

    const int tid = threadIdx.x;
    const int m0  = blockIdx.x * 64;

    gemm_chunk(x, agg, 16, W1,  0, m0, 1.f, sAT, sW, acc, tid);
    gemm_chunk(x, agg, 16, W1, 32, m0, 1.f, sAT, sW, acc, tid);

    const int rg = (tid >> 4) * 4;
    const int cg = (tid & 15) * 8;
#pragma unroll
    for (int i = 0; i < 4; i++) {
        int gr = m0 + rg + i;
        if (gr < N_NODES) {
            float o[8];
#pragma unroll
            for (int j = 0; j < 8; j++)
                o[j] = gelu_exact(acc[i][j] + b1[cg + j]);
            *(float4*)&tptr[(size_t)gr * EMB + cg]     = *(float4*)&o[0];
            *(float4*)&tptr[(size_t)gr * EMB + cg + 4] = *(float4*)&o[4];
        }
    }
}

// ---------------------------------------------------------------------------
// N2: out = 0.5*(t_out@W2_out + b2_out) + 0.5*(t_in@W2_in + b2_in) + x@Wr + br
// ---------------------------------------------------------------------------
__global__ __launch_bounds__(256) void n2_kernel(
    const float* __restrict__ x,
    const float* __restrict__ W2_in,  const float* __restrict__ b2_in,
    const float* __restrict__ W2_out, const float* __restrict__ b2_out,
    const float* __restrict__ Wr,     const float* __restrict__ br,
    float* __restrict__ out)
{
    __shared__ float sAT[32][65];
    __shared__ float sW[32][128];
    float acc[4][8];
#pragma unroll
    for (int i = 0; i < 4; i++)
#pragma unroll
        for (int j = 0; j < 8; j++) acc[i][j] = 0.f;

    const int tid = threadIdx.x;
    const int m0  = blockIdx.x * 64;

#pragma unroll 1
    for (int k0 = 0; k0 < 128; k0 += 32)
        gemm_chunk(g_t[1], nullptr, 32, W2_out, k0, m0, 0.5f, sAT, sW, acc, tid);
#pragma unroll 1
    for (int k0 = 0; k0 < 128; k0 += 32)
        gemm_chunk(g_t[0], nullptr, 32, W2_in, k0, m0, 0.5f, sAT, sW, acc, tid);
#pragma unroll 1
    for (int k0 = 0; k0 < 64; k0 += 32)
        gemm_chunk(x, nullptr, 16, Wr, k0, m0, 1.f, sAT, sW, acc, tid);

    const int rg = (tid >> 4) * 4;
    const int cg = (tid & 15) * 8;
#pragma unroll
    for (int i = 0; i < 4; i++) {
        int gr = m0 + rg + i;
        if (gr < N_NODES) {
            float o[8];
#pragma unroll
            for (int j = 0; j < 8; j++) {
                float bias = 0.5f * (b2_out[cg + j] + b2_in[cg + j]) + br[cg + j];
                o[j] = acc[i][j] + bias;
            }
            *(float4*)&out[(size_t)gr * EMB + cg]     = *(float4*)&o[0];
            *(float4*)&out[(size_t)gr * EMB + cg + 4] = *(float4*)&o[4];
        }
    }
}

// ---------------------------------------------------------------------------
// launch
// ---------------------------------------------------------------------------
extern "C" void kernel_launch(void* const* d_in, const int* in_sizes, int n_in,
                              void* d_out, int out_size)
{
    const float* x      = (const float*)d_in[0];
    const int*   ei     = (const int*)d_in[1];
    const float* ea     = (const float*)d_in[2];
    const float* We_in  = (const float*)d_in[3];
    const float* be_in  = (const float*)d_in[4];
    const float* W1_in  = (const float*)d_in[5];
    const float* b1_in  = (const float*)d_in[6];
    const float* W2_in  = (const float*)d_in[7];
    const float* b2_in  = (const float*)d_in[8];
    const float* We_out = (const float*)d_in[9];
    const float* be_out = (const float*)d_in[10];
    const float* W1_out = (const float*)d_in[11];
    const float* b1_out = (const float*)d_in[12];
    const float* W2_out = (const float*)d_in[13];
    const float* b2_out = (const float*)d_in[14];
    const float* Wr     = (const float*)d_in[15];
    const float* br     = (const float*)d_in[16];
    float* out = (float*)d_out;

    zero_kernel<<<1024, 256>>>();

    dim3 egrid(2368, 2);
    edge_kernel<<<egrid, 256>>>(
        (const float2*)x, ei, ea,
        (const float2*)We_in,  (const float2*)be_in,
        (const float2*)We_out, (const float2*)be_out);

    dim3 ngrid((N_NODES + 63) / 64, 2);
    n1_kernel<<<ngrid, 256>>>(x, W1_in, b1_in, W1_out, b1_out);

    n2_kernel<<<(N_NODES + 63) / 64, 256>>>(
        x, W2_in, b2_in, W2_out, b2_out, Wr, br, out);
}

// round 5
// speedup vs baseline: 2.0004x; 1.2922x over previous
#include <cuda_runtime.h>
#include <math.h>

#define N_NODES 100000
#define N_EDGES 1600000
#define IN_DIM  64
#define EMB     128
#define ED      32

// Scratch (static device allocations are allowed)
__device__ float g_agg[2][(size_t)N_NODES * IN_DIM];   // [0]=in (agg@dst), [1]=out (agg@src)
__device__ float g_t[2][(size_t)N_NODES * EMB];        // gelu(h@W1+b1) per direction

// ---------------------------------------------------------------------------
// zero the aggregation buffers
// ---------------------------------------------------------------------------
__global__ void zero_kernel() {
    size_t total = (size_t)2 * N_NODES * IN_DIM / 4;
    float4* p = (float4*)g_agg;
    float4 z = make_float4(0.f, 0.f, 0.f, 0.f);
    for (size_t i = (size_t)blockIdx.x * blockDim.x + threadIdx.x; i < total;
         i += (size_t)gridDim.x * blockDim.x)
        p[i] = z;
}

// ---------------------------------------------------------------------------
// Edge kernel: warp-per-edge, 4 edges in flight per warp per iteration.
// msg = relu(x[gather] + ea@We + be), red.v2 per lane into agg[scatter].
// Weights register-resident (thread lane owns output dims {2l, 2l+1}).
// ---------------------------------------------------------------------------
__global__ __launch_bounds__(256, 2) void edge_kernel(
    const float2* __restrict__ x2,        // x viewed as [N_NODES][32] float2
    const int* __restrict__ ei,           // [2][N_EDGES] int32
    const float* __restrict__ ea,         // [N_EDGES][32]
    const float2* __restrict__ We_in2,    // [32][32] float2 view of [32][64]
    const float2* __restrict__ be_in2,    // [32]
    const float2* __restrict__ We_out2,
    const float2* __restrict__ be_out2)
{
    const int dir  = blockIdx.y;          // 0 = conv_in, 1 = conv_out
    const int lane = threadIdx.x & 31;
    const int w    = threadIdx.x >> 5;

    const float2* We2 = dir ? We_out2 : We_in2;
    const float2  bias = dir ? be_out2[lane] : be_in2[lane];
    // conv_in:  gather src (ei[0]), scatter dst (ei[1])
    // conv_out: gather dst, scatter src
    const int* gidx = dir ? (ei + N_EDGES) : ei;
    const int* sidx = dir ? ei : (ei + N_EDGES);
    float* __restrict__ agg = g_agg[dir];

    float2 wreg[32];
#pragma unroll
    for (int k = 0; k < 32; k++) wreg[k] = We2[k * 32 + lane];

    __shared__ float sEa[8][4][32];

    const int warpGlobal = blockIdx.x * 8 + w;
    const int nwarps = gridDim.x * 8;

    for (int e0 = warpGlobal; e0 < N_EDGES; e0 += 4 * nwarps) {
        int  ee[4];
        bool hv[4];
        int  dd[4];
#pragma unroll
        for (int i = 0; i < 4; i++) {
            ee[i] = e0 + i * nwarps;
            hv[i] = (ee[i] < N_EDGES);
        }

        // issue all long-latency loads up front (max MLP)
        int ss[4];
#pragma unroll
        for (int i = 0; i < 4; i++) {
            ss[i] = hv[i] ? gidx[ee[i]] : 0;
            dd[i] = hv[i] ? sidx[ee[i]] : 0;
        }
        float2 acc[4];
#pragma unroll
        for (int i = 0; i < 4; i++)
            acc[i] = x2[(size_t)ss[i] * 32 + lane];
        float eav[4];
#pragma unroll
        for (int i = 0; i < 4; i++)
            eav[i] = hv[i] ? ea[(size_t)ee[i] * 32 + lane] : 0.f;

#pragma unroll
        for (int i = 0; i < 4; i++)
            sEa[w][i][lane] = eav[i];
        __syncwarp();

#pragma unroll
        for (int i = 0; i < 4; i++) {
            acc[i].x += bias.x;
            acc[i].y += bias.y;
        }
#pragma unroll
        for (int k = 0; k < 32; k++) {
            float a0 = sEa[w][0][k];
            float a1 = sEa[w][1][k];
            float a2 = sEa[w][2][k];
            float a3 = sEa[w][3][k];
            acc[0].x = fmaf(a0, wreg[k].x, acc[0].x);
            acc[0].y = fmaf(a0, wreg[k].y, acc[0].y);
            acc[1].x = fmaf(a1, wreg[k].x, acc[1].x);
            acc[1].y = fmaf(a1, wreg[k].y, acc[1].y);
            acc[2].x = fmaf(a2, wreg[k].x, acc[2].x);
            acc[2].y = fmaf(a2, wreg[k].y, acc[2].y);
            acc[3].x = fmaf(a3, wreg[k].x, acc[3].x);
            acc[3].y = fmaf(a3, wreg[k].y, acc[3].y);
        }

#pragma unroll
        for (int i = 0; i < 4; i++) {
            if (hv[i]) {
                float mx = fmaxf(acc[i].x, 0.f);
                float my = fmaxf(acc[i].y, 0.f);
                float* p = agg + (size_t)dd[i] * 64 + 2 * lane;
                asm volatile("red.global.add.v2.f32 [%0], {%1, %2};"
                             :: "l"(p), "f"(mx), "f"(my) : "memory");
            }
        }
        __syncwarp();
    }
}

// ---------------------------------------------------------------------------
// GEMM micro-framework: 64(M) x 128(N) block tile, 256 threads, 4x8 microtile,
// K processed in 32-wide chunks. A optionally has an addend and a scale.
// ---------------------------------------------------------------------------
__device__ __forceinline__ void gemm_chunk(
    const float* __restrict__ A, const float* __restrict__ Aadd, int lda4,
    const float* __restrict__ W, int k0, int m0, float scale,
    float (*sAT)[65], float (*sW)[128], float acc[4][8], int tid)
{
    // Stage A chunk: 64 rows x 32 cols, transposed into sAT[k][row]
    const float4* A4  = (const float4*)A;
    const float4* Aa4 = (const float4*)Aadd;
#pragma unroll
    for (int it = 0; it < 2; ++it) {
        int idx = it * 256 + tid;       // 0..511
        int r   = idx >> 3;             // row within tile
        int cq  = idx & 7;              // float4 index within 32-col chunk
        float4 v = make_float4(0.f, 0.f, 0.f, 0.f);
        int gr = m0 + r;
        if (gr < N_NODES) {
            v = A4[(size_t)gr * lda4 + (k0 >> 2) + cq];
            if (Aadd) {
                float4 u = Aa4[(size_t)gr * lda4 + (k0 >> 2) + cq];
                v.x += u.x; v.y += u.y; v.z += u.z; v.w += u.w;
            }
            v.x *= scale; v.y *= scale; v.z *= scale; v.w *= scale;
        }
        sAT[cq * 4 + 0][r] = v.x;
        sAT[cq * 4 + 1][r] = v.y;
        sAT[cq * 4 + 2][r] = v.z;
        sAT[cq * 4 + 3][r] = v.w;
    }
    // Stage W chunk: rows k0..k0+31 of [K][128]
    const float4* W4 = (const float4*)W;
#pragma unroll
    for (int it = 0; it < 4; ++it) {
        int idx = it * 256 + tid;       // 0..1023
        int kr  = idx >> 5;
        int cq  = idx & 31;
        *(float4*)&sW[kr][cq * 4] = W4[(size_t)(k0 + kr) * 32 + cq];
    }
    __syncthreads();

    const int rg = (tid >> 4) * 4;
    const int cg = (tid & 15) * 8;
#pragma unroll
    for (int k = 0; k < 32; k++) {
        float av[4];
        av[0] = sAT[k][rg + 0];
        av[1] = sAT[k][rg + 1];
        av[2] = sAT[k][rg + 2];
        av[3] = sAT[k][rg + 3];
        float bv[8];
        *(float4*)&bv[0] = *(const float4*)&sW[k][cg];
        *(float4*)&bv[4] = *(const float4*)&sW[k][cg + 4];
#pragma unroll
        for (int i = 0; i < 4; i++)
#pragma unroll
            for (int j = 0; j < 8; j++)
                acc[i][j] = fmaf(av[i], bv[j], acc[i][j]);
    }
    __syncthreads();
}

__device__ __forceinline__ float gelu_exact(float v) {
    return 0.5f * v * (1.f + erff(v * 0.70710678118654752f));
}

// ---------------------------------------------------------------------------
// N1: t[dir] = gelu((x + agg[dir]) @ W1 + b1)
// ---------------------------------------------------------------------------
__global__ __launch_bounds__(256) void n1_kernel(
    const float* __restrict__ x,
    const float* __restrict__ W1_in,  const float* __restrict__ b1_in,
    const float* __restrict__ W1_out, const float* __restrict__ b1_out)
{
    const int dir = blockIdx.y;
    const float* W1 = dir ? W1_out : W1_in;
    const float* b1 = dir ? b1_out : b1_in;
    const float* agg = g_agg[dir];
    float* tptr = g_t[dir];

    __shared__ float sAT[32][65];
    __shared__ float sW[32][128];
    float acc[4][8];
#pragma unroll
    for (int i = 0; i < 4; i++)
#pragma unroll
        for (int j = 0; j < 8; j++) acc[i][j] = 0.f;

    const int tid = threadIdx.x;
    const int m0  = blockIdx.x * 64;

    gemm_chunk(x, agg, 16, W1,  0, m0, 1.f, sAT, sW, acc, tid);
    gemm_chunk(x, agg, 16, W1, 32, m0, 1.f, sAT, sW, acc, tid);

    const int rg = (tid >> 4) * 4;
    const int cg = (tid & 15) * 8;
#pragma unroll
    for (int i = 0; i < 4; i++) {
        int gr = m0 + rg + i;
        if (gr < N_NODES) {
            float o[8];
#pragma unroll
            for (int j = 0; j < 8; j++)
                o[j] = gelu_exact(acc[i][j] + b1[cg + j]);
            *(float4*)&tptr[(size_t)gr * EMB + cg]     = *(float4*)&o[0];
            *(float4*)&tptr[(size_t)gr * EMB + cg + 4] = *(float4*)&o[4];
        }
    }
}

// ---------------------------------------------------------------------------
// N2: out = 0.5*(t_out@W2_out + b2_out) + 0.5*(t_in@W2_in + b2_in) + x@Wr + br
// ---------------------------------------------------------------------------
__global__ __launch_bounds__(256) void n2_kernel(
    const float* __restrict__ x,
    const float* __restrict__ W2_in,  const float* __restrict__ b2_in,
    const float* __restrict__ W2_out, const float* __restrict__ b2_out,
    const float* __restrict__ Wr,     const float* __restrict__ br,
    float* __restrict__ out)
{
    __shared__ float sAT[32][65];
    __shared__ float sW[32][128];
    float acc[4][8];
#pragma unroll
    for (int i = 0; i < 4; i++)
#pragma unroll
        for (int j = 0; j < 8; j++) acc[i][j] = 0.f;

    const int tid = threadIdx.x;
    const int m0  = blockIdx.x * 64;

#pragma unroll 1
    for (int k0 = 0; k0 < 128; k0 += 32)
        gemm_chunk(g_t[1], nullptr, 32, W2_out, k0, m0, 0.5f, sAT, sW, acc, tid);
#pragma unroll 1
    for (int k0 = 0; k0 < 128; k0 += 32)
        gemm_chunk(g_t[0], nullptr, 32, W2_in, k0, m0, 0.5f, sAT, sW, acc, tid);
#pragma unroll 1
    for (int k0 = 0; k0 < 64; k0 += 32)
        gemm_chunk(x, nullptr, 16, Wr, k0, m0, 1.f, sAT, sW, acc, tid);

    const int rg = (tid >> 4) * 4;
    const int cg = (tid & 15) * 8;
#pragma unroll
    for (int i = 0; i < 4; i++) {
        int gr = m0 + rg + i;
        if (gr < N_NODES) {
            float o[8];
#pragma unroll
            for (int j = 0; j < 8; j++) {
                float bias = 0.5f * (b2_out[cg + j] + b2_in[cg + j]) + br[cg + j];
                o[j] = acc[i][j] + bias;
            }
            *(float4*)&out[(size_t)gr * EMB + cg]     = *(float4*)&o[0];
            *(float4*)&out[(size_t)gr * EMB + cg + 4] = *(float4*)&o[4];
        }
    }
}

// ---------------------------------------------------------------------------
// launch
// ---------------------------------------------------------------------------
extern "C" void kernel_launch(void* const* d_in, const int* in_sizes, int n_in,
                              void* d_out, int out_size)
{
    const float* x      = (const float*)d_in[0];
    const int*   ei     = (const int*)d_in[1];
    const float* ea     = (const float*)d_in[2];
    const float* We_in  = (const float*)d_in[3];
    const float* be_in  = (const float*)d_in[4];
    const float* W1_in  = (const float*)d_in[5];
    const float* b1_in  = (const float*)d_in[6];
    const float* W2_in  = (const float*)d_in[7];
    const float* b2_in  = (const float*)d_in[8];
    const float* We_out = (const float*)d_in[9];
    const float* be_out = (const float*)d_in[10];
    const float* W1_out = (const float*)d_in[11];
    const float* b1_out = (const float*)d_in[12];
    const float* W2_out = (const float*)d_in[13];
    const float* b2_out = (const float*)d_in[14];
    const float* Wr     = (const float*)d_in[15];
    const float* br     = (const float*)d_in[16];
    float* out = (float*)d_out;

    zero_kernel<<<1024, 256>>>();

    dim3 egrid(2368, 2);
    edge_kernel<<<egrid, 256>>>(
        (const float2*)x, ei, ea,
        (const float2*)We_in,  (const float2*)be_in,
        (const float2*)We_out, (const float2*)be_out);

    dim3 ngrid((N_NODES + 63) / 64, 2);
    n1_kernel<<<ngrid, 256>>>(x, W1_in, b1_in, W1_out, b1_out);

    n2_kernel<<<(N_NODES + 63) / 64, 256>>>(
        x, W2_in, b2_in, W2_out, b2_out, Wr, br, out);
}

// round 6
// speedup vs baseline: 2.1310x; 1.0653x over previous
#include <cuda_runtime.h>
#include <math.h>

#define N_NODES 100000
#define N_EDGES 1600000
#define IN_DIM  64
#define EMB     128
#define ED      32

__device__ float g_agg[2][(size_t)N_NODES * IN_DIM];   // [0]=in (agg@dst), [1]=out (agg@src)
__device__ float g_t[2][(size_t)N_NODES * EMB];        // gelu(h@W1+b1) per direction

// ---------------------------------------------------------------------------
// zero the aggregation buffers
// ---------------------------------------------------------------------------
__global__ void zero_kernel() {
    size_t total = (size_t)2 * N_NODES * IN_DIM / 4;
    float4* p = (float4*)g_agg;
    float4 z = make_float4(0.f, 0.f, 0.f, 0.f);
    for (size_t i = (size_t)blockIdx.x * blockDim.x + threadIdx.x; i < total;
         i += (size_t)gridDim.x * blockDim.x)
        p[i] = z;
}

// ---------------------------------------------------------------------------
// Edge kernel: warp-per-edge, 4 edges in flight. Compute in registers
// (2 dims/lane, register-resident weights), then stage results in shared and
// issue red.global.add.v4 (16 lane-ops per edge instead of 32).
// ---------------------------------------------------------------------------
__global__ __launch_bounds__(256, 2) void edge_kernel(
    const float2* __restrict__ x2,        // x as [N_NODES][32] float2
    const int* __restrict__ ei,           // [2][N_EDGES] int32
    const float* __restrict__ ea,         // [N_EDGES][32]
    const float2* __restrict__ We_in2,    // [32][32] float2 view of [32][64]
    const float2* __restrict__ be_in2,
    const float2* __restrict__ We_out2,
    const float2* __restrict__ be_out2)
{
    const int dir  = blockIdx.y;
    const int lane = threadIdx.x & 31;
    const int w    = threadIdx.x >> 5;

    const float2* We2 = dir ? We_out2 : We_in2;
    const float2  bias = dir ? be_out2[lane] : be_in2[lane];
    const int* gidx = dir ? (ei + N_EDGES) : ei;
    const int* sidx = dir ? ei : (ei + N_EDGES);
    float* __restrict__ agg = g_agg[dir];

    float2 wreg[32];
#pragma unroll
    for (int k = 0; k < 32; k++) wreg[k] = We2[k * 32 + lane];

    __shared__ float sEa[8][4][32];
    __shared__ float sAcc[8][4][64];

    const int warpGlobal = blockIdx.x * 8 + w;
    const int nwarps = gridDim.x * 8;

    for (int e0 = warpGlobal; e0 < N_EDGES; e0 += 4 * nwarps) {
        int  ee[4];
        bool hv[4];
        int  dd[4];
#pragma unroll
        for (int i = 0; i < 4; i++) {
            ee[i] = e0 + i * nwarps;
            hv[i] = (ee[i] < N_EDGES);
        }

        int ss[4];
#pragma unroll
        for (int i = 0; i < 4; i++) {
            ss[i] = hv[i] ? gidx[ee[i]] : 0;
            dd[i] = hv[i] ? sidx[ee[i]] : 0;
        }
        float2 acc[4];
#pragma unroll
        for (int i = 0; i < 4; i++)
            acc[i] = x2[(size_t)ss[i] * 32 + lane];
        float eav[4];
#pragma unroll
        for (int i = 0; i < 4; i++)
            eav[i] = hv[i] ? ea[(size_t)ee[i] * 32 + lane] : 0.f;

#pragma unroll
        for (int i = 0; i < 4; i++)
            sEa[w][i][lane] = eav[i];
        __syncwarp();

#pragma unroll
        for (int i = 0; i < 4; i++) {
            acc[i].x += bias.x;
            acc[i].y += bias.y;
        }
#pragma unroll
        for (int k = 0; k < 32; k++) {
            float a0 = sEa[w][0][k];
            float a1 = sEa[w][1][k];
            float a2 = sEa[w][2][k];
            float a3 = sEa[w][3][k];
            acc[0].x = fmaf(a0, wreg[k].x, acc[0].x);
            acc[0].y = fmaf(a0, wreg[k].y, acc[0].y);
            acc[1].x = fmaf(a1, wreg[k].x, acc[1].x);
            acc[1].y = fmaf(a1, wreg[k].y, acc[1].y);
            acc[2].x = fmaf(a2, wreg[k].x, acc[2].x);
            acc[2].y = fmaf(a2, wreg[k].y, acc[2].y);
            acc[3].x = fmaf(a3, wreg[k].x, acc[3].x);
            acc[3].y = fmaf(a3, wreg[k].y, acc[3].y);
        }

        // relu + stage to shared
#pragma unroll
        for (int i = 0; i < 4; i++) {
            float2 r;
            r.x = fmaxf(acc[i].x, 0.f);
            r.y = fmaxf(acc[i].y, 0.f);
            *(float2*)&sAcc[w][i][2 * lane] = r;
        }
        __syncwarp();

        // chunk c = lane: edge lane>>4, chunk c2 = lane+32: edge 2+(lane>>4)
        const int ehi = lane >> 4;
        const int off = (lane & 15) * 4;
        float4 v1 = *(const float4*)&sAcc[w][ehi][off];
        float4 v2 = *(const float4*)&sAcc[w][2 + ehi][off];
        int  d1 = ehi ? dd[1] : dd[0];
        int  d2 = ehi ? dd[3] : dd[2];
        bool h1 = ehi ? hv[1] : hv[0];
        bool h2 = ehi ? hv[3] : hv[2];

        if (h1) {
            float* p = agg + (size_t)d1 * 64 + off;
            asm volatile("red.global.add.v4.f32 [%0], {%1, %2, %3, %4};"
                         :: "l"(p), "f"(v1.x), "f"(v1.y), "f"(v1.z), "f"(v1.w)
                         : "memory");
        }
        if (h2) {
            float* p = agg + (size_t)d2 * 64 + off;
            asm volatile("red.global.add.v4.f32 [%0], {%1, %2, %3, %4};"
                         :: "l"(p), "f"(v2.x), "f"(v2.y), "f"(v2.z), "f"(v2.w)
                         : "memory");
        }
        __syncwarp();
    }
}

// ---------------------------------------------------------------------------
// GEMM: 128(M) x 128(N) block tile, 256 threads, 8x8 microtile,
// K in 32-wide chunks. A row-major staged (sA[128][36]); W [32][128].
// ---------------------------------------------------------------------------
__device__ __forceinline__ void gemm_chunk128(
    const float* __restrict__ A, const float* __restrict__ Aadd, int lda4,
    const float* __restrict__ W, int k0, int m0, float scale,
    float (*sA)[36], float (*sW)[128], float acc[8][8], int tid)
{
    const float4* A4  = (const float4*)A;
    const float4* Aa4 = (const float4*)Aadd;
#pragma unroll
    for (int it = 0; it < 4; ++it) {
        int idx = it * 256 + tid;       // 0..1023
        int r   = idx >> 3;             // row 0..127
        int cq  = idx & 7;              // float4 col within 32-chunk
        float4 v = make_float4(0.f, 0.f, 0.f, 0.f);
        int gr = m0 + r;
        if (gr < N_NODES) {
            v = A4[(size_t)gr * lda4 + (k0 >> 2) + cq];
            if (Aadd) {
                float4 u = Aa4[(size_t)gr * lda4 + (k0 >> 2) + cq];
                v.x += u.x; v.y += u.y; v.z += u.z; v.w += u.w;
            }
            v.x *= scale; v.y *= scale; v.z *= scale; v.w *= scale;
        }
        *(float4*)&sA[r][cq * 4] = v;
    }
    const float4* W4 = (const float4*)W;
#pragma unroll
    for (int it = 0; it < 4; ++it) {
        int idx = it * 256 + tid;       // 0..1023
        int kr  = idx >> 5;
        int cq  = idx & 31;
        *(float4*)&sW[kr][cq * 4] = W4[(size_t)(k0 + kr) * 32 + cq];
    }
    __syncthreads();

    const int rg = (tid >> 4) * 8;
    const int cg = (tid & 15) * 8;
#pragma unroll
    for (int k = 0; k < 32; k++) {
        float av[8];
#pragma unroll
        for (int i = 0; i < 8; i++) av[i] = sA[rg + i][k];
        float bv[8];
        *(float4*)&bv[0] = *(const float4*)&sW[k][cg];
        *(float4*)&bv[4] = *(const float4*)&sW[k][cg + 4];
#pragma unroll
        for (int i = 0; i < 8; i++)
#pragma unroll
            for (int j = 0; j < 8; j++)
                acc[i][j] = fmaf(av[i], bv[j], acc[i][j]);
    }
    __syncthreads();
}

__device__ __forceinline__ float gelu_exact(float v) {
    return 0.5f * v * (1.f + erff(v * 0.70710678118654752f));
}

// ---------------------------------------------------------------------------
// N1: t[dir] = gelu((x + agg[dir]) @ W1 + b1)
// ---------------------------------------------------------------------------
__global__ __launch_bounds__(256, 2) void n1_kernel(
    const float* __restrict__ x,
    const float* __restrict__ W1_in,  const float* __restrict__ b1_in,
    const float* __restrict__ W1_out, const float* __restrict__ b1_out)
{
    const int dir = blockIdx.y;
    const float* W1 = dir ? W1_out : W1_in;
    const float* b1 = dir ? b1_out : b1_in;
    const float* agg = g_agg[dir];
    float* tptr = g_t[dir];

    __shared__ float sA[128][36];
    __shared__ float sW[32][128];
    float acc[8][8];
#pragma unroll
    for (int i = 0; i < 8; i++)
#pragma unroll
        for (int j = 0; j < 8; j++) acc[i][j] = 0.f;

    const int tid = threadIdx.x;
    const int m0  = blockIdx.x * 128;

    gemm_chunk128(x, agg, 16, W1,  0, m0, 1.f, sA, sW, acc, tid);
    gemm_chunk128(x, agg, 16, W1, 32, m0, 1.f, sA, sW, acc, tid);

    const int rg = (tid >> 4) * 8;
    const int cg = (tid & 15) * 8;
#pragma unroll
    for (int i = 0; i < 8; i++) {
        int gr = m0 + rg + i;
        if (gr < N_NODES) {
            float o[8];
#pragma unroll
            for (int j = 0; j < 8; j++)
                o[j] = gelu_exact(acc[i][j] + b1[cg + j]);
            *(float4*)&tptr[(size_t)gr * EMB + cg]     = *(float4*)&o[0];
            *(float4*)&tptr[(size_t)gr * EMB + cg + 4] = *(float4*)&o[4];
        }
    }
}

// ---------------------------------------------------------------------------
// N2: out = 0.5*(t_out@W2_out + b2_out) + 0.5*(t_in@W2_in + b2_in) + x@Wr + br
// ---------------------------------------------------------------------------
__global__ __launch_bounds__(256, 2) void n2_kernel(
    const float* __restrict__ x,
    const float* __restrict__ W2_in,  const float* __restrict__ b2_in,
    const float* __restrict__ W2_out, const float* __restrict__ b2_out,
    const float* __restrict__ Wr,     const float* __restrict__ br,
    float* __restrict__ out)
{
    __shared__ float sA[128][36];
    __shared__ float sW[32][128];
    float acc[8][8];
#pragma unroll
    for (int i = 0; i < 8; i++)
#pragma unroll
        for (int j = 0; j < 8; j++) acc[i][j] = 0.f;

    const int tid = threadIdx.x;
    const int m0  = blockIdx.x * 128;

#pragma unroll 1
    for (int k0 = 0; k0 < 128; k0 += 32)
        gemm_chunk128(g_t[1], nullptr, 32, W2_out, k0, m0, 0.5f, sA, sW, acc, tid);
#pragma unroll 1
    for (int k0 = 0; k0 < 128; k0 += 32)
        gemm_chunk128(g_t[0], nullptr, 32, W2_in, k0, m0, 0.5f, sA, sW, acc, tid);
#pragma unroll 1
    for (int k0 = 0; k0 < 64; k0 += 32)
        gemm_chunk128(x, nullptr, 16, Wr, k0, m0, 1.f, sA, sW, acc, tid);

    const int rg = (tid >> 4) * 8;
    const int cg = (tid & 15) * 8;
#pragma unroll
    for (int i = 0; i < 8; i++) {
        int gr = m0 + rg + i;
        if (gr < N_NODES) {
            float o[8];
#pragma unroll
            for (int j = 0; j < 8; j++) {
                float bias = 0.5f * (b2_out[cg + j] + b2_in[cg + j]) + br[cg + j];
                o[j] = acc[i][j] + bias;
            }
            *(float4*)&out[(size_t)gr * EMB + cg]     = *(float4*)&o[0];
            *(float4*)&out[(size_t)gr * EMB + cg + 4] = *(float4*)&o[4];
        }
    }
}

// ---------------------------------------------------------------------------
// launch
// ---------------------------------------------------------------------------
extern "C" void kernel_launch(void* const* d_in, const int* in_sizes, int n_in,
                              void* d_out, int out_size)
{
    const float* x      = (const float*)d_in[0];
    const int*   ei     = (const int*)d_in[1];
    const float* ea     = (const float*)d_in[2];
    const float* We_in  = (const float*)d_in[3];
    const float* be_in  = (const float*)d_in[4];
    const float* W1_in  = (const float*)d_in[5];
    const float* b1_in  = (const float*)d_in[6];
    const float* W2_in  = (const float*)d_in[7];
    const float* b2_in  = (const float*)d_in[8];
    const float* We_out = (const float*)d_in[9];
    const float* be_out = (const float*)d_in[10];
    const float* W1_out = (const float*)d_in[11];
    const float* b1_out = (const float*)d_in[12];
    const float* W2_out = (const float*)d_in[13];
    const float* b2_out = (const float*)d_in[14];
    const float* Wr     = (const float*)d_in[15];
    const float* br     = (const float*)d_in[16];
    float* out = (float*)d_out;

    zero_kernel<<<1024, 256>>>();

    dim3 egrid(2368, 2);
    edge_kernel<<<egrid, 256>>>(
        (const float2*)x, ei, ea,
        (const float2*)We_in,  (const float2*)be_in,
        (const float2*)We_out, (const float2*)be_out);

    dim3 ngrid((N_NODES + 127) / 128, 2);
    n1_kernel<<<ngrid, 256>>>(x, W1_in, b1_in, W1_out, b1_out);

    n2_kernel<<<(N_NODES + 127) / 128, 256>>>(
        x, W2_in, b2_in, W2_out, b2_out, Wr, br, out);
}